// round 13
// baseline (speedup 1.0000x reference)
#include <cuda_runtime.h>
#include <cuda_fp16.h>
#include <math.h>
#include <stdint.h>

#define NTOK 8192
#define DIM  1024
#define VD   32
#define KCB  4096

// ---------------- device scratch ----------------
__device__ __half g_ehl[KCB * 64];      // codebook normalized: [k][hi 0:32 | lo 32:64]
__device__ __half g_hphl[NTOK * 64];    // hp normalized:       [t][hi 0:32 | lo 32:64]
__device__ __half g_wphl[32 * 2048];    // Wp  split: [v][hi k 0:1024 | lo k 1024:2048]
__device__ __half g_wpihl[1024 * 64];   // Wpi split: [d][hi v 0:32 | lo v 32:64]
__device__ float  g_py[2 * NTOK * VD];  // partial unnormalized y per ksplit
__device__ float  g_pz[2 * NTOK];       // partial Z
__device__ float  g_pbv[2 * NTOK];      // partial argmax value
__device__ int    g_pbk[2 * NTOK];      // partial argmax index

// ---------------- helpers ----------------
__device__ __forceinline__ float warpSum(float v) {
#pragma unroll
    for (int o = 16; o; o >>= 1) v += __shfl_xor_sync(0xffffffffu, v, o);
    return v;
}
__device__ __forceinline__ uint32_t smaddr(const void* p) {
    return (uint32_t)__cvta_generic_to_shared(p);
}
__device__ __forceinline__ void ldmx4(uint32_t* r, uint32_t a) {
    asm volatile("ldmatrix.sync.aligned.m8n8.x4.shared.b16 {%0,%1,%2,%3}, [%4];"
                 : "=r"(r[0]), "=r"(r[1]), "=r"(r[2]), "=r"(r[3]) : "r"(a));
}
__device__ __forceinline__ void ldmx4t(uint32_t* r, uint32_t a) {
    asm volatile("ldmatrix.sync.aligned.m8n8.x4.trans.shared.b16 {%0,%1,%2,%3}, [%4];"
                 : "=r"(r[0]), "=r"(r[1]), "=r"(r[2]), "=r"(r[3]) : "r"(a));
}
__device__ __forceinline__ void mmaf16(float* c, const uint32_t* a, const uint32_t* b) {
    asm volatile("mma.sync.aligned.m16n8k16.row.col.f32.f16.f16.f32 "
                 "{%0,%1,%2,%3}, {%4,%5,%6,%7}, {%8,%9}, {%0,%1,%2,%3};"
                 : "+f"(c[0]), "+f"(c[1]), "+f"(c[2]), "+f"(c[3])
                 : "r"(a[0]), "r"(a[1]), "r"(a[2]), "r"(a[3]), "r"(b[0]), "r"(b[1]));
}
__device__ __forceinline__ uint32_t packh2(float lo, float hi) {
    uint32_t r; asm("cvt.rn.f16x2.f32 %0, %1, %2;" : "=r"(r) : "f"(hi), "f"(lo)); return r;
}
__device__ __forceinline__ uint32_t ex2h2(uint32_t a) {
    uint32_t r; asm("ex2.approx.f16x2 %0, %1;" : "=r"(r) : "r"(a)); return r;
}
__device__ __forceinline__ void cpa16(uint32_t dst, const void* src) {
    asm volatile("cp.async.cg.shared.global [%0], [%1], 16;" :: "r"(dst), "l"(src));
}
#define CP_COMMIT() asm volatile("cp.async.commit_group;" ::: "memory")
#define CP_WAIT(n)  asm volatile("cp.async.wait_group %0;" :: "n"(n) : "memory")

__device__ __forceinline__ void hsplit(float x, __half& hi, __half& lo) {
    hi = __float2half_rn(x);
    lo = __float2half_rn(x - __half2float(hi));
}

// ---------------- Kernel P: prep (codebook normalize + weight splits) ----------------
// grid 640: blocks [0,512) embnorm, [512,640) weight split.
__global__ void k_prep(const float* __restrict__ emb,
                       const float* __restrict__ Wp,
                       const float* __restrict__ Wpi) {
    int b = blockIdx.x, tid = threadIdx.x;
    if (b < 512) {
        int row  = b * 8 + (tid >> 5);
        int lane = tid & 31;
        float x  = emb[row * VD + lane];
        float ss = warpSum(x * x);
        float xn = x * rsqrtf(ss);
        __half hi, lo; hsplit(xn, hi, lo);
        g_ehl[(size_t)row * 64 + lane]      = hi;
        g_ehl[(size_t)row * 64 + 32 + lane] = lo;
    } else {
        int i = (b - 512) * 256 + tid;
        {   // Wp [32][1024]
            int v = i >> 10, k = i & 1023;
            __half hi, lo; hsplit(Wp[v * 1024 + k], hi, lo);
            g_wphl[(size_t)v * 2048 + k]        = hi;
            g_wphl[(size_t)v * 2048 + 1024 + k] = lo;
        }
        {   // Wpi [1024][32]
            int d = i >> 5, v = i & 31;
            __half hi, lo; hsplit(Wpi[d * 32 + v], hi, lo);
            g_wpihl[(size_t)d * 64 + v]      = hi;
            g_wpihl[(size_t)d * 64 + 32 + v] = lo;
        }
    }
}

// ---------------- Kernel B: hp = normalize(h @ Wp^T + bp) on tensor cores ----------------
// grid 256, block 256 (8 warps). CTA: 32 tokens x 32 v, K=1024 in 16 chunks of 64.
// h fp32 staged via double-buffered cp.async, converted to fp16 hi/lo in smem.
__global__ void __launch_bounds__(256) k_proj(const float* __restrict__ h,
                                              const float* __restrict__ bp) {
    __shared__ __align__(16) float  hf[2][32][64];   // h fp32 chunk
    __shared__ __align__(16) __half wb[2][64][72];   // Wp chunk: rows 0:32 hi, 32:64 lo
    __shared__ __align__(16) __half ah[32][72];      // h hi
    __shared__ __align__(16) __half al[32][72];      // h lo
    __shared__ __align__(16) float  hpb[32][33];

    const int tid = threadIdx.x, wid = tid >> 5, lane = tid & 31;
    const int t0 = blockIdx.x * 32;
    const int mb = wid >> 2, nq = wid & 3;
    const int g = lane >> 2, t4 = lane & 3;

    const int pr = tid >> 3, pc8 = tid & 7;      // convert/copy mapping

    // prefetch chunk 0
    {
#pragma unroll
        for (int j = 0; j < 2; j++) {
            int i = tid + j * 256, r = i >> 4, c4 = (i & 15) * 4;
            cpa16(smaddr(&hf[0][r][c4]), h + (size_t)(t0 + r) * DIM + c4);
            cpa16(smaddr(&wb[0][j * 32 + pr][pc8 * 8]),
                  g_wphl + (size_t)pr * 2048 + j * 1024 + pc8 * 8);
        }
        CP_COMMIT();
    }

    float c[4] = {0.f, 0.f, 0.f, 0.f};

    for (int ch = 0; ch < 16; ch++) {
        const int cur = ch & 1;
        CP_WAIT(0);
        __syncthreads();
        if (ch + 1 < 16) {
            int nb = 1 - cur;
#pragma unroll
            for (int j = 0; j < 2; j++) {
                int i = tid + j * 256, r = i >> 4, c4 = (i & 15) * 4;
                cpa16(smaddr(&hf[nb][r][c4]),
                      h + (size_t)(t0 + r) * DIM + (ch + 1) * 64 + c4);
                cpa16(smaddr(&wb[nb][j * 32 + pr][pc8 * 8]),
                      g_wphl + (size_t)pr * 2048 + j * 1024 + (ch + 1) * 64 + pc8 * 8);
            }
            CP_COMMIT();
        }
        // convert h fp32 -> hi/lo halves (cooperative)
        {
            float4 f0 = *(const float4*)&hf[cur][pr][pc8 * 8];
            float4 f1 = *(const float4*)&hf[cur][pr][pc8 * 8 + 4];
            __half h0, l0, h1, l1, h2, l2, h3, l3;
            hsplit(f0.x, h0, l0); hsplit(f0.y, h1, l1);
            hsplit(f0.z, h2, l2); hsplit(f0.w, h3, l3);
            __half hh[4] = {h0, h1, h2, h3};
            __half ll[4] = {l0, l1, l2, l3};
            *(uint2*)&ah[pr][pc8 * 8] = *(uint2*)hh;
            *(uint2*)&al[pr][pc8 * 8] = *(uint2*)ll;
            hsplit(f1.x, h0, l0); hsplit(f1.y, h1, l1);
            hsplit(f1.z, h2, l2); hsplit(f1.w, h3, l3);
            __half hh2[4] = {h0, h1, h2, h3};
            __half ll2[4] = {l0, l1, l2, l3};
            *(uint2*)&ah[pr][pc8 * 8 + 4] = *(uint2*)hh2;
            *(uint2*)&al[pr][pc8 * 8 + 4] = *(uint2*)ll2;
        }
        __syncthreads();

        // A fragments (4 ksteps hi, 4 lo)
        uint32_t a_hi[4][4], a_lo[4][4];
        {
            int r = mb * 16 + ((lane >> 3) & 1) * 8 + (lane & 7);
            int cb = (lane >> 4) * 8;
#pragma unroll
            for (int ks = 0; ks < 4; ks++) {
                ldmx4(a_hi[ks], smaddr(&ah[r][ks * 16 + cb]));
                ldmx4(a_lo[ks], smaddr(&al[r][ks * 16 + cb]));
            }
        }
        // B fragments: n8 tile (v = nq*8..+8), k 0..63, hi + lo planes
        uint32_t bh_a[4], bh_b[4], bl_a[4], bl_b[4];
        {
            int r = nq * 8 + (lane & 7);
            int cc = ((lane >> 3) & 1) * 8 + (lane >> 4) * 16;
            uint32_t adh = smaddr(&wb[cur][r][cc]);
            uint32_t adl = smaddr(&wb[cur][32 + r][cc]);
            ldmx4(bh_a, adh); ldmx4(bh_b, adh + 64);
            ldmx4(bl_a, adl); ldmx4(bl_b, adl + 64);
        }
        mmaf16(c, a_hi[0], bh_a + 0); mmaf16(c, a_hi[1], bh_a + 2);
        mmaf16(c, a_hi[2], bh_b + 0); mmaf16(c, a_hi[3], bh_b + 2);
        mmaf16(c, a_lo[0], bh_a + 0); mmaf16(c, a_lo[1], bh_a + 2);
        mmaf16(c, a_lo[2], bh_b + 0); mmaf16(c, a_lo[3], bh_b + 2);
        mmaf16(c, a_hi[0], bl_a + 0); mmaf16(c, a_hi[1], bl_a + 2);
        mmaf16(c, a_hi[2], bl_b + 0); mmaf16(c, a_hi[3], bl_b + 2);
    }

    // write C frags, normalize
    {
        int r = mb * 16 + g, cc = nq * 8 + t4 * 2;
        hpb[r][cc] = c[0];     hpb[r][cc + 1] = c[1];
        hpb[r + 8][cc] = c[2]; hpb[r + 8][cc + 1] = c[3];
    }
    __syncthreads();
#pragma unroll
    for (int q = 0; q < 4; q++) {
        int t = wid * 4 + q;
        float x = hpb[t][lane] + bp[lane];
        float ss = warpSum(x * x);
        float xn = x * rsqrtf(ss);
        __half hi, lo; hsplit(xn, hi, lo);
        g_hphl[(size_t)(t0 + t) * 64 + lane]      = hi;
        g_hphl[(size_t)(t0 + t) * 64 + 32 + lane] = lo;
    }
}

// ---------------- Kernel C: VQ core on tensor cores (mma.sync f16) ----------------
// grid 256 = 128 token-tiles x 2 code-splits; block 256 (8 warps).
// Single barrier per chunk; f16x2 ex2 softmax.
__global__ void __launch_bounds__(256, 2) k_vq(void) {
    struct Epi { float ys[64][33]; float zs[64]; float bvs[64]; int bks[64]; };
    __shared__ __align__(16) unsigned char pool_[2 * 128 * 72 * 2];  // 36864B
    __half (*e_s)[128][72] = reinterpret_cast<__half(*)[128][72]>(pool_);
    Epi* epi = reinterpret_cast<Epi*>(pool_);
    __shared__ __align__(16) __half hp_s[64][72];

    const int tid = threadIdx.x, wid = tid >> 5, lane = tid & 31;
    const int tileIdx = blockIdx.x >> 1;
    const int ks = blockIdx.x & 1;
    const int t0 = tileIdx * 64;
    const int cbase = ks * 16;
    const int mb = wid >> 1, nh = wid & 1;
    const int g  = lane >> 2, t4 = lane & 3;

    // prefetch chunk 0 into buf 0
#pragma unroll
    for (int j = 0; j < 4; j++) {
        int i = tid + j * 256, r = i >> 3, c8 = i & 7;
        cpa16(smaddr(&e_s[0][r][c8 * 8]),
              (const char*)g_ehl + ((size_t)(cbase * 128 + r) * 64 + c8 * 8) * 2);
    }
    CP_COMMIT();

    for (int i = tid; i < 512; i += 256) {
        int r = i >> 3, cc = i & 7;
        *(float4*)&hp_s[r][cc * 8] = ((const float4*)g_hphl)[(size_t)(t0 + r) * 8 + cc];
    }
    __syncthreads();

    uint32_t a_hi[2][4], a_lo[2][4];
    {
        int r = mb * 16 + ((lane >> 3) & 1) * 8 + (lane & 7);
        int cb = (lane >> 4) * 8;
        ldmx4(a_hi[0], smaddr(&hp_s[r][0  + cb]));
        ldmx4(a_hi[1], smaddr(&hp_s[r][16 + cb]));
        ldmx4(a_lo[0], smaddr(&hp_s[r][32 + cb]));
        ldmx4(a_lo[1], smaddr(&hp_s[r][48 + cb]));
    }

    float yacc[4][4];
#pragma unroll
    for (int i = 0; i < 4; i++)
#pragma unroll
        for (int q = 0; q < 4; q++) yacc[i][q] = 0.f;
    float z0 = 0.f, z1 = 0.f;
    float bv0 = -INFINITY, bv1 = -INFINITY;
    int   bk0 = 0, bk1 = 0;

    const int sb_row = nh * 64 + (lane & 7);
    const int sb_col = ((lane >> 3) & 1) * 8 + (lane >> 4) * 16;
    const int ab_rofs = nh * 64 + ((lane >> 3) & 1) * 8 + (lane & 7);
    const int ab_c8   = (lane >> 4) * 8;

    for (int ci = 0; ci < 16; ci++) {
        const int cur = ci & 1;
        const int c = cbase + ci;
        CP_WAIT(0);
        __syncthreads();          // data visible + everyone done with other buffer
        if (ci + 1 < 16) {
            int nb = 1 - cur;
            const char* src = (const char*)g_ehl + (size_t)(c + 1) * 128 * 128;
#pragma unroll
            for (int j = 0; j < 4; j++) {
                int i = tid + j * 256, r = i >> 3, c8 = i & 7;
                cpa16(smaddr(&e_s[nb][r][c8 * 8]), src + ((size_t)r * 64 + c8 * 8) * 2);
            }
            CP_COMMIT();
        }

        // ---- score pass ----
        uint32_t pk[8][2];
#pragma unroll
        for (int j = 0; j < 8; j++) {
            float s[4] = {0.f, 0.f, 0.f, 0.f};
            uint32_t bh[4], bl[4];
            uint32_t ad = smaddr(&e_s[cur][sb_row + j * 8][sb_col]);
            ldmx4(bh, ad);
            ldmx4(bl, ad + 64);
            mmaf16(s, a_hi[0], bh + 0); mmaf16(s, a_hi[1], bh + 2);
            mmaf16(s, a_lo[0], bh + 0); mmaf16(s, a_lo[1], bh + 2);
            mmaf16(s, a_hi[0], bl + 0); mmaf16(s, a_hi[1], bl + 2);

            int code0 = c * 128 + nh * 64 + j * 8 + t4 * 2;
            if (s[0] > bv0) { bv0 = s[0]; bk0 = code0; }
            if (s[1] > bv0) { bv0 = s[1]; bk0 = code0 + 1; }
            if (s[2] > bv1) { bv1 = s[2]; bk1 = code0; }
            if (s[3] > bv1) { bv1 = s[3]; bk1 = code0 + 1; }
            // p = exp(2s-2) = 2^((s-1)*2/ln2), via f16x2 ex2
            float a0 = fmaf(s[0], 2.885390082f, -2.885390082f);
            float a1 = fmaf(s[1], 2.885390082f, -2.885390082f);
            float a2 = fmaf(s[2], 2.885390082f, -2.885390082f);
            float a3 = fmaf(s[3], 2.885390082f, -2.885390082f);
            uint32_t p01 = ex2h2(packh2(a0, a1));
            uint32_t p23 = ex2h2(packh2(a2, a3));
            __half2 h01 = *(__half2*)&p01;
            __half2 h23 = *(__half2*)&p23;
            z0 += __low2float(h01) + __high2float(h01);
            z1 += __low2float(h23) + __high2float(h23);
            pk[j][0] = p01;
            pk[j][1] = p23;
        }

        // ---- accumulate pass: y += P @ E_hi ----
#pragma unroll
        for (int kc = 0; kc < 4; kc++) {
            uint32_t A[4] = {pk[2*kc][0], pk[2*kc][1], pk[2*kc+1][0], pk[2*kc+1][1]};
            int crow = ab_rofs + kc * 16;
#pragma unroll
            for (int vtp = 0; vtp < 2; vtp++) {
                uint32_t bh[4];
                uint32_t ad = smaddr(&e_s[cur][crow][vtp * 16 + ab_c8]);
                ldmx4t(bh, ad);
                mmaf16(yacc[vtp*2+0], A, bh + 0); mmaf16(yacc[vtp*2+1], A, bh + 2);
            }
        }
    }

    // ---- quad reductions ----
    z0 += __shfl_xor_sync(0xffffffffu, z0, 1); z0 += __shfl_xor_sync(0xffffffffu, z0, 2);
    z1 += __shfl_xor_sync(0xffffffffu, z1, 1); z1 += __shfl_xor_sync(0xffffffffu, z1, 2);
#pragma unroll
    for (int o = 1; o <= 2; o <<= 1) {
        float ob = __shfl_xor_sync(0xffffffffu, bv0, o);
        int   ok = __shfl_xor_sync(0xffffffffu, bk0, o);
        if (ob > bv0 || (ob == bv0 && ok < bk0)) { bv0 = ob; bk0 = ok; }
        ob = __shfl_xor_sync(0xffffffffu, bv1, o);
        ok = __shfl_xor_sync(0xffffffffu, bk1, o);
        if (ob > bv1 || (ob == bv1 && ok < bk1)) { bv1 = ob; bk1 = ok; }
    }

    int r0 = mb * 16 + g, r1 = r0 + 8;
    if (nh == 1) {   // epi aliases buffer 0; last compute used buffer 1 — safe
        if (t4 == 0) {
            epi->zs[r0] = z0; epi->bvs[r0] = bv0; epi->bks[r0] = bk0;
            epi->zs[r1] = z1; epi->bvs[r1] = bv1; epi->bks[r1] = bk1;
        }
#pragma unroll
        for (int vt = 0; vt < 4; vt++) {
            int cc = vt * 8 + t4 * 2;
            epi->ys[r0][cc] = yacc[vt][0]; epi->ys[r0][cc + 1] = yacc[vt][1];
            epi->ys[r1][cc] = yacc[vt][2]; epi->ys[r1][cc + 1] = yacc[vt][3];
        }
    }
    __syncthreads();
    if (nh == 0) {
        float Z0 = z0 + epi->zs[r0], Z1 = z1 + epi->zs[r1];
        {
            float ob = epi->bvs[r0]; int ok = epi->bks[r0];
            if (ob > bv0 || (ob == bv0 && ok < bk0)) { bv0 = ob; bk0 = ok; }
            ob = epi->bvs[r1]; ok = epi->bks[r1];
            if (ob > bv1 || (ob == bv1 && ok < bk1)) { bv1 = ob; bk1 = ok; }
        }
        int tok0 = t0 + r0, tok1 = t0 + r1;
        size_t base = (size_t)ks * NTOK;
#pragma unroll
        for (int vt = 0; vt < 4; vt++) {
            int cc = vt * 8 + t4 * 2;
            g_py[(base + tok0) * VD + cc]     = yacc[vt][0] + epi->ys[r0][cc];
            g_py[(base + tok0) * VD + cc + 1] = yacc[vt][1] + epi->ys[r0][cc + 1];
            g_py[(base + tok1) * VD + cc]     = yacc[vt][2] + epi->ys[r1][cc];
            g_py[(base + tok1) * VD + cc + 1] = yacc[vt][3] + epi->ys[r1][cc + 1];
        }
        if (t4 == 0) {
            g_pz[base + tok0] = Z0;  g_pz[base + tok1] = Z1;
            g_pbv[base + tok0] = bv0; g_pbv[base + tok1] = bv1;
            g_pbk[base + tok0] = bk0; g_pbk[base + tok1] = bk1;
        }
    }
}

// ---------------- Kernel D: merge partials + out = hvq @ Wpi^T + bpi + codes ----------
// grid 256, block 256. CTA: 32 tokens x all 1024 d (8 chunks of 128 d rows).
__global__ void __launch_bounds__(256, 2) k_out(const float* __restrict__ bpi,
                                                const float* __restrict__ attn_mask,
                                                float* __restrict__ out,
                                                int write_codes, int write_loss) {
    __shared__ __align__(16) __half eb[2][128][72];  // Wpi chunk [d][hi|lo]
    __shared__ __align__(16) __half ah[32][72];      // hvq [tok][hi 0:32 | lo 32:64]

    const int tid = threadIdx.x, wid = tid >> 5, lane = tid & 31;
    const int t0 = blockIdx.x * 32;
    const int mb = wid >> 2, nq = wid & 3;
    const int g = lane >> 2, t4 = lane & 3;

    // prefetch Wpi chunk 0
#pragma unroll
    for (int j = 0; j < 4; j++) {
        int i = tid + j * 256, r = i >> 3, c8 = i & 7;
        cpa16(smaddr(&eb[0][r][c8 * 8]), g_wpihl + (size_t)r * 64 + c8 * 8);
    }
    CP_COMMIT();

    // merge partials -> hvq -> hi/lo smem
    {
        int r = tid >> 3, c4 = (tid & 7) * 4;
        int tok = t0 + r;
        float4 y0 = *(const float4*)&g_py[(size_t)tok * VD + c4];
        float4 y1 = *(const float4*)&g_py[(size_t)(NTOK + tok) * VD + c4];
        float Z = g_pz[tok] + g_pz[NTOK + tok];
        float inv = (attn_mask[tok] == 1.0f) ? 1.0f / Z : 0.0f;
        float v0 = (y0.x + y1.x) * inv, v1 = (y0.y + y1.y) * inv;
        float v2 = (y0.z + y1.z) * inv, v3 = (y0.w + y1.w) * inv;
        __half h0, l0, h1, l1, h2, l2, h3, l3;
        hsplit(v0, h0, l0); hsplit(v1, h1, l1);
        hsplit(v2, h2, l2); hsplit(v3, h3, l3);
        __half hh[4] = {h0, h1, h2, h3};
        __half ll[4] = {l0, l1, l2, l3};
        *(uint2*)&ah[r][c4]      = *(uint2*)hh;
        *(uint2*)&ah[r][32 + c4] = *(uint2*)ll;
    }
    // folded tail: codes + loss
    if (write_codes && tid < 32) {
        int tok = t0 + tid;
        float bv0 = g_pbv[tok], bv1 = g_pbv[NTOK + tok];
        int   bk0 = g_pbk[tok], bk1 = g_pbk[NTOK + tok];
        int code = (bv1 > bv0) ? bk1 : bk0;   // tie -> lower index (split 0)
        out[(size_t)NTOK * DIM + tok] = (attn_mask[tok] == 1.0f) ? (float)code : 0.0f;
        if (write_loss && blockIdx.x == 0 && tid == 0)
            out[(size_t)NTOK * DIM + NTOK] = 0.0f;
    }
    __syncthreads();

    uint32_t a_hi[2][4], a_lo[2][4];
    {
        int r = mb * 16 + ((lane >> 3) & 1) * 8 + (lane & 7);
        int cb = (lane >> 4) * 8;
        ldmx4(a_hi[0], smaddr(&ah[r][0  + cb]));
        ldmx4(a_hi[1], smaddr(&ah[r][16 + cb]));
        ldmx4(a_lo[0], smaddr(&ah[r][32 + cb]));
        ldmx4(a_lo[1], smaddr(&ah[r][48 + cb]));
    }

    const int sb_row = nq * 32 + (lane & 7);
    const int sb_col = ((lane >> 3) & 1) * 8 + (lane >> 4) * 16;

    for (int ci = 0; ci < 8; ci++) {
        const int cur = ci & 1;
        CP_WAIT(0);
        __syncthreads();
        if (ci + 1 < 8) {
            int nb = 1 - cur;
            const __half* src = g_wpihl + (size_t)(ci + 1) * 128 * 64;
#pragma unroll
            for (int j = 0; j < 4; j++) {
                int i = tid + j * 256, r = i >> 3, c8 = i & 7;
                cpa16(smaddr(&eb[nb][r][c8 * 8]), src + (size_t)r * 64 + c8 * 8);
            }
            CP_COMMIT();
        }

#pragma unroll
        for (int j = 0; j < 4; j++) {
            float c[4] = {0.f, 0.f, 0.f, 0.f};
            uint32_t bh[4], bl[4];
            uint32_t ad = smaddr(&eb[cur][sb_row + j * 8][sb_col]);
            ldmx4(bh, ad);
            ldmx4(bl, ad + 64);
            mmaf16(c, a_hi[0], bh + 0); mmaf16(c, a_hi[1], bh + 2);
            mmaf16(c, a_lo[0], bh + 0); mmaf16(c, a_lo[1], bh + 2);
            mmaf16(c, a_hi[0], bl + 0); mmaf16(c, a_hi[1], bl + 2);

            int d = ci * 128 + nq * 32 + j * 8 + t4 * 2;
            float b0 = __ldg(&bpi[d]), b1 = __ldg(&bpi[d + 1]);
            int r0 = t0 + mb * 16 + g;
            float2 o0 = {c[0] + b0, c[1] + b1};
            float2 o1 = {c[2] + b0, c[3] + b1};
            *(float2*)&out[(size_t)r0 * DIM + d]       = o0;
            *(float2*)&out[(size_t)(r0 + 8) * DIM + d] = o1;
        }
    }
}

// ---------------- launch ----------------
extern "C" void kernel_launch(void* const* d_in, const int* in_sizes, int n_in,
                              void* d_out, int out_size) {
    const float* h    = (const float*)d_in[0];
    const float* mask = (const float*)d_in[1];
    const float* Wp   = (const float*)d_in[2];
    const float* bp   = (const float*)d_in[3];
    const float* Wpi  = (const float*)d_in[4];
    const float* bpi  = (const float*)d_in[5];
    const float* emb  = (const float*)d_in[6];
    float* out = (float*)d_out;

    long long need = (long long)NTOK * DIM;
    int wc = ((long long)out_size >= need + NTOK) ? 1 : 0;
    int wl = ((long long)out_size >= need + NTOK + 1) ? 1 : 0;

    k_prep<<<640, 256>>>(emb, Wp, Wpi);
    k_proj<<<256, 256>>>(h, bp);
    k_vq<<<256, 256>>>();
    k_out<<<256, 256>>>(bpi, mask, out, wc, wl);
}

// round 16
// speedup vs baseline: 1.0277x; 1.0277x over previous
#include <cuda_runtime.h>
#include <cuda_fp16.h>
#include <math.h>
#include <stdint.h>

#define NTOK 8192
#define DIM  1024
#define VD   32
#define KCB  4096

// ---------------- device scratch ----------------
__device__ __half g_ehl[KCB * 64];      // codebook normalized: [k][hi 0:32 | lo 32:64]
__device__ __half g_hphl[NTOK * 64];    // hp normalized:       [t][hi 0:32 | lo 32:64]
__device__ __half g_wphl[32 * 2048];    // Wp  split: [v][hi k 0:1024 | lo k 1024:2048]
__device__ __half g_wpihl[1024 * 64];   // Wpi split: [d][hi v 0:32 | lo v 32:64]
__device__ float  g_py[2 * NTOK * VD];  // partial unnormalized y per ksplit
__device__ float  g_pz[2 * NTOK];       // partial Z
__device__ float  g_pbv[2 * NTOK];      // partial argmax value
__device__ int    g_pbk[2 * NTOK];      // partial argmax index

// ---------------- helpers ----------------
__device__ __forceinline__ float warpSum(float v) {
#pragma unroll
    for (int o = 16; o; o >>= 1) v += __shfl_xor_sync(0xffffffffu, v, o);
    return v;
}
__device__ __forceinline__ uint32_t smaddr(const void* p) {
    return (uint32_t)__cvta_generic_to_shared(p);
}
__device__ __forceinline__ void ldmx4(uint32_t* r, uint32_t a) {
    asm volatile("ldmatrix.sync.aligned.m8n8.x4.shared.b16 {%0,%1,%2,%3}, [%4];"
                 : "=r"(r[0]), "=r"(r[1]), "=r"(r[2]), "=r"(r[3]) : "r"(a));
}
__device__ __forceinline__ void ldmx4t(uint32_t* r, uint32_t a) {
    asm volatile("ldmatrix.sync.aligned.m8n8.x4.trans.shared.b16 {%0,%1,%2,%3}, [%4];"
                 : "=r"(r[0]), "=r"(r[1]), "=r"(r[2]), "=r"(r[3]) : "r"(a));
}
__device__ __forceinline__ void mmaf16(float* c, const uint32_t* a, const uint32_t* b) {
    asm volatile("mma.sync.aligned.m16n8k16.row.col.f32.f16.f16.f32 "
                 "{%0,%1,%2,%3}, {%4,%5,%6,%7}, {%8,%9}, {%0,%1,%2,%3};"
                 : "+f"(c[0]), "+f"(c[1]), "+f"(c[2]), "+f"(c[3])
                 : "r"(a[0]), "r"(a[1]), "r"(a[2]), "r"(a[3]), "r"(b[0]), "r"(b[1]));
}
__device__ __forceinline__ uint32_t packh2(float lo, float hi) {
    uint32_t r; asm("cvt.rn.f16x2.f32 %0, %1, %2;" : "=r"(r) : "f"(hi), "f"(lo)); return r;
}
__device__ __forceinline__ uint32_t ex2h2(uint32_t a) {
    uint32_t r; asm("ex2.approx.f16x2 %0, %1;" : "=r"(r) : "r"(a)); return r;
}
__device__ __forceinline__ void cpa16(uint32_t dst, const void* src) {
    asm volatile("cp.async.cg.shared.global [%0], [%1], 16;" :: "r"(dst), "l"(src));
}
#define CP_COMMIT() asm volatile("cp.async.commit_group;" ::: "memory")
#define CP_WAIT(n)  asm volatile("cp.async.wait_group %0;" :: "n"(n) : "memory")

__device__ __forceinline__ void hsplit(float x, __half& hi, __half& lo) {
    hi = __float2half_rn(x);
    lo = __float2half_rn(x - __half2float(hi));
}

// ---------------- Kernel P: prep (codebook normalize + weight splits) ----------------
__global__ void k_prep(const float* __restrict__ emb,
                       const float* __restrict__ Wp,
                       const float* __restrict__ Wpi) {
    int b = blockIdx.x, tid = threadIdx.x;
    if (b < 512) {
        int row  = b * 8 + (tid >> 5);
        int lane = tid & 31;
        float x  = emb[row * VD + lane];
        float ss = warpSum(x * x);
        float xn = x * rsqrtf(ss);
        __half hi, lo; hsplit(xn, hi, lo);
        g_ehl[(size_t)row * 64 + lane]      = hi;
        g_ehl[(size_t)row * 64 + 32 + lane] = lo;
    } else {
        int i = (b - 512) * 256 + tid;
        {   // Wp [32][1024]
            int v = i >> 10, k = i & 1023;
            __half hi, lo; hsplit(Wp[v * 1024 + k], hi, lo);
            g_wphl[(size_t)v * 2048 + k]        = hi;
            g_wphl[(size_t)v * 2048 + 1024 + k] = lo;
        }
        {   // Wpi [1024][32]
            int d = i >> 5, v = i & 31;
            __half hi, lo; hsplit(Wpi[d * 32 + v], hi, lo);
            g_wpihl[(size_t)d * 64 + v]      = hi;
            g_wpihl[(size_t)d * 64 + 32 + v] = lo;
        }
    }
}

// ---------------- Kernel B: hp = normalize(h @ Wp^T + bp) on tensor cores ----------------
// grid 256, block 256 (8 warps). CTA: 32 tokens x 32 v, K=1024 in 16 chunks of 64.
// h loaded direct from global (fp32), split in registers. ~20KB smem -> 2 CTAs/SM.
__global__ void __launch_bounds__(256) k_proj(const float* __restrict__ h,
                                              const float* __restrict__ bp) {
    __shared__ __align__(16) __half ah[32][72];   // h hi   [tok][k 0:64]
    __shared__ __align__(16) __half al[32][72];   // h lo
    __shared__ __align__(16) __half wh[32][72];   // Wp hi  [v][k 0:64]
    __shared__ __align__(16) __half wl[32][72];   // Wp lo
    __shared__ __align__(16) float  hpb[32][36];

    const int tid = threadIdx.x, wid = tid >> 5, lane = tid & 31;
    const int t0 = blockIdx.x * 32;
    const int mb = wid >> 2, nq = wid & 3;
    const int g = lane >> 2, t4 = lane & 3;

    float c[4] = {0.f, 0.f, 0.f, 0.f};

    const int cvrow = tid >> 3;          // 0..31 token row
    const int cvseg = tid & 7;           // 8-col segment

    for (int ch = 0; ch < 16; ch++) {
        __syncthreads();
        // cp.async Wp chunk (hi+lo planes)
#pragma unroll
        for (int j = 0; j < 2; j++) {
            int i = tid + j * 256;
            int pl = i >> 8, r = (i >> 3) & 31, c8 = i & 7;
            cpa16(smaddr(pl ? &wl[r][c8 * 8] : &wh[r][c8 * 8]),
                  g_wphl + (size_t)r * 2048 + pl * 1024 + ch * 64 + c8 * 8);
        }
        CP_COMMIT();
        // load h fp32 direct, split, store to smem
        {
            const float* src = h + (size_t)(t0 + cvrow) * DIM + ch * 64 + cvseg * 8;
#pragma unroll
            for (int q = 0; q < 2; q++) {
                float4 f = *(const float4*)(src + q * 4);
                __half h0, l0, h1, l1, h2, l2, h3, l3;
                hsplit(f.x, h0, l0); hsplit(f.y, h1, l1);
                hsplit(f.z, h2, l2); hsplit(f.w, h3, l3);
                __half hh[4] = {h0, h1, h2, h3};
                __half ll[4] = {l0, l1, l2, l3};
                *(uint2*)&ah[cvrow][cvseg * 8 + q * 4] = *(uint2*)hh;
                *(uint2*)&al[cvrow][cvseg * 8 + q * 4] = *(uint2*)ll;
            }
        }
        CP_WAIT(0);
        __syncthreads();

        // A fragments (4 ksteps hi, 4 lo)
        uint32_t a_hi[4][4], a_lo[4][4];
        {
            int r = mb * 16 + ((lane >> 3) & 1) * 8 + (lane & 7);
            int cb = (lane >> 4) * 8;
#pragma unroll
            for (int ks = 0; ks < 4; ks++) {
                ldmx4(a_hi[ks], smaddr(&ah[r][ks * 16 + cb]));
                ldmx4(a_lo[ks], smaddr(&al[r][ks * 16 + cb]));
            }
        }
        // B fragments: one n8 tile (v = nq*8..nq*8+7), k 0..63
        uint32_t bh_a[4], bh_b[4], bl_a[4], bl_b[4];
        {
            int r = nq * 8 + (lane & 7);
            int cc = ((lane >> 3) & 1) * 8 + (lane >> 4) * 16;
            uint32_t adh = smaddr(&wh[r][cc]);
            uint32_t adl = smaddr(&wl[r][cc]);
            ldmx4(bh_a, adh); ldmx4(bh_b, adh + 64);
            ldmx4(bl_a, adl); ldmx4(bl_b, adl + 64);
        }
        mmaf16(c, a_hi[0], bh_a + 0); mmaf16(c, a_hi[1], bh_a + 2);
        mmaf16(c, a_hi[2], bh_b + 0); mmaf16(c, a_hi[3], bh_b + 2);
        mmaf16(c, a_lo[0], bh_a + 0); mmaf16(c, a_lo[1], bh_a + 2);
        mmaf16(c, a_lo[2], bh_b + 0); mmaf16(c, a_lo[3], bh_b + 2);
        mmaf16(c, a_hi[0], bl_a + 0); mmaf16(c, a_hi[1], bl_a + 2);
        mmaf16(c, a_hi[2], bl_b + 0); mmaf16(c, a_hi[3], bl_b + 2);
    }

    // write C frags, normalize
    {
        int r = mb * 16 + g, cc = nq * 8 + t4 * 2;
        hpb[r][cc] = c[0];     hpb[r][cc + 1] = c[1];
        hpb[r + 8][cc] = c[2]; hpb[r + 8][cc + 1] = c[3];
    }
    __syncthreads();
#pragma unroll
    for (int q = 0; q < 4; q++) {
        int t = wid * 4 + q;
        float x = hpb[t][lane] + bp[lane];
        float ss = warpSum(x * x);
        float xn = x * rsqrtf(ss);
        __half hi, lo; hsplit(xn, hi, lo);
        g_hphl[(size_t)(t0 + t) * 64 + lane]      = hi;
        g_hphl[(size_t)(t0 + t) * 64 + 32 + lane] = lo;
    }
}

// ---------------- Kernel C: VQ core on tensor cores (mma.sync f16) ----------------
// grid 256 = 128 token-tiles x 2 code-splits; block 256 (8 warps).
// Single barrier per chunk; f16x2 ex2 softmax.
__global__ void __launch_bounds__(256, 2) k_vq(void) {
    struct Epi { float ys[64][33]; float zs[64]; float bvs[64]; int bks[64]; };
    __shared__ __align__(16) unsigned char pool_[2 * 128 * 72 * 2];  // 36864B
    __half (*e_s)[128][72] = reinterpret_cast<__half(*)[128][72]>(pool_);
    Epi* epi = reinterpret_cast<Epi*>(pool_);
    __shared__ __align__(16) __half hp_s[64][72];

    const int tid = threadIdx.x, wid = tid >> 5, lane = tid & 31;
    const int tileIdx = blockIdx.x >> 1;
    const int ks = blockIdx.x & 1;
    const int t0 = tileIdx * 64;
    const int cbase = ks * 16;
    const int mb = wid >> 1, nh = wid & 1;
    const int g  = lane >> 2, t4 = lane & 3;

    // prefetch chunk 0 into buf 0
#pragma unroll
    for (int j = 0; j < 4; j++) {
        int i = tid + j * 256, r = i >> 3, c8 = i & 7;
        cpa16(smaddr(&e_s[0][r][c8 * 8]),
              (const char*)g_ehl + ((size_t)(cbase * 128 + r) * 64 + c8 * 8) * 2);
    }
    CP_COMMIT();

    for (int i = tid; i < 512; i += 256) {
        int r = i >> 3, cc = i & 7;
        *(float4*)&hp_s[r][cc * 8] = ((const float4*)g_hphl)[(size_t)(t0 + r) * 8 + cc];
    }
    __syncthreads();

    uint32_t a_hi[2][4], a_lo[2][4];
    {
        int r = mb * 16 + ((lane >> 3) & 1) * 8 + (lane & 7);
        int cb = (lane >> 4) * 8;
        ldmx4(a_hi[0], smaddr(&hp_s[r][0  + cb]));
        ldmx4(a_hi[1], smaddr(&hp_s[r][16 + cb]));
        ldmx4(a_lo[0], smaddr(&hp_s[r][32 + cb]));
        ldmx4(a_lo[1], smaddr(&hp_s[r][48 + cb]));
    }

    float yacc[4][4];
#pragma unroll
    for (int i = 0; i < 4; i++)
#pragma unroll
        for (int q = 0; q < 4; q++) yacc[i][q] = 0.f;
    float z0 = 0.f, z1 = 0.f;
    float bv0 = -INFINITY, bv1 = -INFINITY;
    int   bk0 = 0, bk1 = 0;

    const int sb_row = nh * 64 + (lane & 7);
    const int sb_col = ((lane >> 3) & 1) * 8 + (lane >> 4) * 16;
    const int ab_rofs = nh * 64 + ((lane >> 3) & 1) * 8 + (lane & 7);
    const int ab_c8   = (lane >> 4) * 8;

    for (int ci = 0; ci < 16; ci++) {
        const int cur = ci & 1;
        const int c = cbase + ci;
        CP_WAIT(0);
        __syncthreads();          // data visible + everyone done with other buffer
        if (ci + 1 < 16) {
            int nb = 1 - cur;
            const char* src = (const char*)g_ehl + (size_t)(c + 1) * 128 * 128;
#pragma unroll
            for (int j = 0; j < 4; j++) {
                int i = tid + j * 256, r = i >> 3, c8 = i & 7;
                cpa16(smaddr(&e_s[nb][r][c8 * 8]), src + ((size_t)r * 64 + c8 * 8) * 2);
            }
            CP_COMMIT();
        }

        // ---- score pass ----
        uint32_t pk[8][2];
#pragma unroll
        for (int j = 0; j < 8; j++) {
            float s[4] = {0.f, 0.f, 0.f, 0.f};
            uint32_t bh[4], bl[4];
            uint32_t ad = smaddr(&e_s[cur][sb_row + j * 8][sb_col]);
            ldmx4(bh, ad);
            ldmx4(bl, ad + 64);
            mmaf16(s, a_hi[0], bh + 0); mmaf16(s, a_hi[1], bh + 2);
            mmaf16(s, a_lo[0], bh + 0); mmaf16(s, a_lo[1], bh + 2);
            mmaf16(s, a_hi[0], bl + 0); mmaf16(s, a_hi[1], bl + 2);

            int code0 = c * 128 + nh * 64 + j * 8 + t4 * 2;
            if (s[0] > bv0) { bv0 = s[0]; bk0 = code0; }
            if (s[1] > bv0) { bv0 = s[1]; bk0 = code0 + 1; }
            if (s[2] > bv1) { bv1 = s[2]; bk1 = code0; }
            if (s[3] > bv1) { bv1 = s[3]; bk1 = code0 + 1; }
            // p = exp(2s-2) = 2^((s-1)*2/ln2), via f16x2 ex2
            float a0 = fmaf(s[0], 2.885390082f, -2.885390082f);
            float a1 = fmaf(s[1], 2.885390082f, -2.885390082f);
            float a2 = fmaf(s[2], 2.885390082f, -2.885390082f);
            float a3 = fmaf(s[3], 2.885390082f, -2.885390082f);
            uint32_t p01 = ex2h2(packh2(a0, a1));
            uint32_t p23 = ex2h2(packh2(a2, a3));
            __half2 h01 = *(__half2*)&p01;
            __half2 h23 = *(__half2*)&p23;
            z0 += __low2float(h01) + __high2float(h01);
            z1 += __low2float(h23) + __high2float(h23);
            pk[j][0] = p01;
            pk[j][1] = p23;
        }

        // ---- accumulate pass: y += P @ E_hi ----
#pragma unroll
        for (int kc = 0; kc < 4; kc++) {
            uint32_t A[4] = {pk[2*kc][0], pk[2*kc][1], pk[2*kc+1][0], pk[2*kc+1][1]};
            int crow = ab_rofs + kc * 16;
#pragma unroll
            for (int vtp = 0; vtp < 2; vtp++) {
                uint32_t bh[4];
                uint32_t ad = smaddr(&e_s[cur][crow][vtp * 16 + ab_c8]);
                ldmx4t(bh, ad);
                mmaf16(yacc[vtp*2+0], A, bh + 0); mmaf16(yacc[vtp*2+1], A, bh + 2);
            }
        }
    }

    // ---- quad reductions ----
    z0 += __shfl_xor_sync(0xffffffffu, z0, 1); z0 += __shfl_xor_sync(0xffffffffu, z0, 2);
    z1 += __shfl_xor_sync(0xffffffffu, z1, 1); z1 += __shfl_xor_sync(0xffffffffu, z1, 2);
#pragma unroll
    for (int o = 1; o <= 2; o <<= 1) {
        float ob = __shfl_xor_sync(0xffffffffu, bv0, o);
        int   ok = __shfl_xor_sync(0xffffffffu, bk0, o);
        if (ob > bv0 || (ob == bv0 && ok < bk0)) { bv0 = ob; bk0 = ok; }
        ob = __shfl_xor_sync(0xffffffffu, bv1, o);
        ok = __shfl_xor_sync(0xffffffffu, bk1, o);
        if (ob > bv1 || (ob == bv1 && ok < bk1)) { bv1 = ob; bk1 = ok; }
    }

    int r0 = mb * 16 + g, r1 = r0 + 8;
    if (nh == 1) {   // epi aliases buffer 0; last compute used buffer 1 — safe
        if (t4 == 0) {
            epi->zs[r0] = z0; epi->bvs[r0] = bv0; epi->bks[r0] = bk0;
            epi->zs[r1] = z1; epi->bvs[r1] = bv1; epi->bks[r1] = bk1;
        }
#pragma unroll
        for (int vt = 0; vt < 4; vt++) {
            int cc = vt * 8 + t4 * 2;
            epi->ys[r0][cc] = yacc[vt][0]; epi->ys[r0][cc + 1] = yacc[vt][1];
            epi->ys[r1][cc] = yacc[vt][2]; epi->ys[r1][cc + 1] = yacc[vt][3];
        }
    }
    __syncthreads();
    if (nh == 0) {
        float Z0 = z0 + epi->zs[r0], Z1 = z1 + epi->zs[r1];
        {
            float ob = epi->bvs[r0]; int ok = epi->bks[r0];
            if (ob > bv0 || (ob == bv0 && ok < bk0)) { bv0 = ob; bk0 = ok; }
            ob = epi->bvs[r1]; ok = epi->bks[r1];
            if (ob > bv1 || (ob == bv1 && ok < bk1)) { bv1 = ob; bk1 = ok; }
        }
        int tok0 = t0 + r0, tok1 = t0 + r1;
        size_t base = (size_t)ks * NTOK;
#pragma unroll
        for (int vt = 0; vt < 4; vt++) {
            int cc = vt * 8 + t4 * 2;
            g_py[(base + tok0) * VD + cc]     = yacc[vt][0] + epi->ys[r0][cc];
            g_py[(base + tok0) * VD + cc + 1] = yacc[vt][1] + epi->ys[r0][cc + 1];
            g_py[(base + tok1) * VD + cc]     = yacc[vt][2] + epi->ys[r1][cc];
            g_py[(base + tok1) * VD + cc + 1] = yacc[vt][3] + epi->ys[r1][cc + 1];
        }
        if (t4 == 0) {
            g_pz[base + tok0] = Z0;  g_pz[base + tok1] = Z1;
            g_pbv[base + tok0] = bv0; g_pbv[base + tok1] = bv1;
            g_pbk[base + tok0] = bk0; g_pbk[base + tok1] = bk1;
        }
    }
}

// ---------------- Kernel D: merge partials + out = hvq @ Wpi^T + bpi + codes ----------
// grid 256, block 256, 3 CTAs/SM (reg-capped to <=85 for latency hiding).
__global__ void __launch_bounds__(256, 3) k_out(const float* __restrict__ bpi,
                                                const float* __restrict__ attn_mask,
                                                float* __restrict__ out,
                                                int write_codes, int write_loss) {
    __shared__ __align__(16) __half eb[2][128][72];  // Wpi chunk [d][hi|lo]
    __shared__ __align__(16) __half ah[32][72];      // hvq [tok][hi 0:32 | lo 32:64]

    const int tid = threadIdx.x, wid = tid >> 5, lane = tid & 31;
    const int t0 = blockIdx.x * 32;
    const int mb = wid >> 2, nq = wid & 3;
    const int g = lane >> 2, t4 = lane & 3;

    // prefetch Wpi chunk 0
#pragma unroll
    for (int j = 0; j < 4; j++) {
        int i = tid + j * 256, r = i >> 3, c8 = i & 7;
        cpa16(smaddr(&eb[0][r][c8 * 8]), g_wpihl + (size_t)r * 64 + c8 * 8);
    }
    CP_COMMIT();

    // merge partials -> hvq -> hi/lo smem
    {
        int r = tid >> 3, c4 = (tid & 7) * 4;
        int tok = t0 + r;
        float4 y0 = *(const float4*)&g_py[(size_t)tok * VD + c4];
        float4 y1 = *(const float4*)&g_py[(size_t)(NTOK + tok) * VD + c4];
        float Z = g_pz[tok] + g_pz[NTOK + tok];
        float inv = (attn_mask[tok] == 1.0f) ? 1.0f / Z : 0.0f;
        float v0 = (y0.x + y1.x) * inv, v1 = (y0.y + y1.y) * inv;
        float v2 = (y0.z + y1.z) * inv, v3 = (y0.w + y1.w) * inv;
        __half h0, l0, h1, l1, h2, l2, h3, l3;
        hsplit(v0, h0, l0); hsplit(v1, h1, l1);
        hsplit(v2, h2, l2); hsplit(v3, h3, l3);
        __half hh[4] = {h0, h1, h2, h3};
        __half ll[4] = {l0, l1, l2, l3};
        *(uint2*)&ah[r][c4]      = *(uint2*)hh;
        *(uint2*)&ah[r][32 + c4] = *(uint2*)ll;
    }
    // folded tail: codes + loss
    if (write_codes && tid < 32) {
        int tok = t0 + tid;
        float bv0 = g_pbv[tok], bv1 = g_pbv[NTOK + tok];
        int   bk0 = g_pbk[tok], bk1 = g_pbk[NTOK + tok];
        int code = (bv1 > bv0) ? bk1 : bk0;   // tie -> lower index (split 0)
        out[(size_t)NTOK * DIM + tok] = (attn_mask[tok] == 1.0f) ? (float)code : 0.0f;
        if (write_loss && blockIdx.x == 0 && tid == 0)
            out[(size_t)NTOK * DIM + NTOK] = 0.0f;
    }
    __syncthreads();

    uint32_t a_hi[2][4], a_lo[2][4];
    {
        int r = mb * 16 + ((lane >> 3) & 1) * 8 + (lane & 7);
        int cb = (lane >> 4) * 8;
        ldmx4(a_hi[0], smaddr(&ah[r][0  + cb]));
        ldmx4(a_hi[1], smaddr(&ah[r][16 + cb]));
        ldmx4(a_lo[0], smaddr(&ah[r][32 + cb]));
        ldmx4(a_lo[1], smaddr(&ah[r][48 + cb]));
    }

    const int sb_row = nq * 32 + (lane & 7);
    const int sb_col = ((lane >> 3) & 1) * 8 + (lane >> 4) * 16;

    for (int ci = 0; ci < 8; ci++) {
        const int cur = ci & 1;
        CP_WAIT(0);
        __syncthreads();
        if (ci + 1 < 8) {
            int nb = 1 - cur;
            const __half* src = g_wpihl + (size_t)(ci + 1) * 128 * 64;
#pragma unroll
            for (int j = 0; j < 4; j++) {
                int i = tid + j * 256, r = i >> 3, c8 = i & 7;
                cpa16(smaddr(&eb[nb][r][c8 * 8]), src + (size_t)r * 64 + c8 * 8);
            }
            CP_COMMIT();
        }

#pragma unroll
        for (int j = 0; j < 4; j++) {
            float c[4] = {0.f, 0.f, 0.f, 0.f};
            uint32_t bh[4], bl[4];
            uint32_t ad = smaddr(&eb[cur][sb_row + j * 8][sb_col]);
            ldmx4(bh, ad);
            ldmx4(bl, ad + 64);
            mmaf16(c, a_hi[0], bh + 0); mmaf16(c, a_hi[1], bh + 2);
            mmaf16(c, a_lo[0], bh + 0); mmaf16(c, a_lo[1], bh + 2);
            mmaf16(c, a_hi[0], bl + 0); mmaf16(c, a_hi[1], bl + 2);

            int d = ci * 128 + nq * 32 + j * 8 + t4 * 2;
            float b0 = __ldg(&bpi[d]), b1 = __ldg(&bpi[d + 1]);
            int r0 = t0 + mb * 16 + g;
            float2 o0 = {c[0] + b0, c[1] + b1};
            float2 o1 = {c[2] + b0, c[3] + b1};
            *(float2*)&out[(size_t)r0 * DIM + d]       = o0;
            *(float2*)&out[(size_t)(r0 + 8) * DIM + d] = o1;
        }
    }
}

// ---------------- launch ----------------
extern "C" void kernel_launch(void* const* d_in, const int* in_sizes, int n_in,
                              void* d_out, int out_size) {
    const float* h    = (const float*)d_in[0];
    const float* mask = (const float*)d_in[1];
    const float* Wp   = (const float*)d_in[2];
    const float* bp   = (const float*)d_in[3];
    const float* Wpi  = (const float*)d_in[4];
    const float* bpi  = (const float*)d_in[5];
    const float* emb  = (const float*)d_in[6];
    float* out = (float*)d_out;

    long long need = (long long)NTOK * DIM;
    int wc = ((long long)out_size >= need + NTOK) ? 1 : 0;
    int wl = ((long long)out_size >= need + NTOK + 1) ? 1 : 0;

    k_prep<<<640, 256>>>(emb, Wp, Wpi);
    k_proj<<<256, 256>>>(h, bp);
    k_vq<<<256, 256>>>();
    k_out<<<256, 256>>>(bpi, mask, out, wc, wl);
}